// round 1
// baseline (speedup 1.0000x reference)
#include <cuda_runtime.h>
#include <cuda_bf16.h>

// ---------------------------------------------------------------------------
// GSMP_4879082848655: GNN step
//   edge MLP: x=[vc[src],vc[dst],ve] (96) -> relu(xW1+b1) (96) -> y=hW2+b2 (129)
//   gate k = sigmoid(y0); f = y[1:129]*k
//   scatter: s1=segsum(f1), m2=segmax(f2), m3=segmin(f3), m4=segmean(f4) onto dst
//   out_vc = [vc,s1,m2,m3,m4] (160) @ Wr + br
//   out_ve = [f, ve] (160) @ We + be
// ---------------------------------------------------------------------------

#define MAXN 100000
#define MAXE 1600000
#define BE   128      // edges per block
#define PADE 132      // padded edge stride (bank-conflict avoidance, keeps 16B align)
#define TPB  256

// scratch accumulators (static device arrays: no allocation allowed)
__device__ float    g_s1[MAXN * 32];
__device__ float    g_m4[MAXN * 32];
__device__ unsigned g_m2[MAXN * 32];
__device__ unsigned g_m3[MAXN * 32];
__device__ float    g_deg[MAXN];

// monotone float <-> uint mapping so atomicMax/atomicMin on unsigned == float max/min
__device__ __forceinline__ unsigned encf(float f) {
    unsigned u = __float_as_uint(f);
    return (u & 0x80000000u) ? ~u : (u | 0x80000000u);
}
__device__ __forceinline__ float decf(unsigned u) {
    u = (u & 0x80000000u) ? (u & 0x7FFFFFFFu) : ~u;
    return __uint_as_float(u);
}

__global__ void init_kernel(int N) {
    int i = blockIdx.x * blockDim.x + threadIdx.x;
    int tot = N * 32;
    if (i < tot) {
        g_s1[i] = 0.f;
        g_m4[i] = 0.f;
        g_m2[i] = 0u;           // encf(-inf) lower bound
        g_m3[i] = 0xFFFFFFFFu;  // encf(+inf) upper bound
    }
    if (i < N) g_deg[i] = 0.f;
}

// smem layout (floats):
//   Xs[96*PADE] Hs[96*PADE] Fs[128*PADE] Ws[12288] Wg[96]
//   B1[96] Bm[128] Bev[32] Ksig[128] Bg[4]
#define SMEM_FLOATS (96*PADE + 96*PADE + 128*PADE + 12288 + 96 + 96 + 128 + 32 + 128 + 4)

__global__ __launch_bounds__(TPB, 1)
void edge_kernel(const float* __restrict__ vc, const float* __restrict__ ve,
                 const int* __restrict__ src, const int* __restrict__ dst,
                 const float* __restrict__ Wm1, const float* __restrict__ bm1,
                 const float* __restrict__ Wm2, const float* __restrict__ bm2,
                 const float* __restrict__ We,  const float* __restrict__ be,
                 float* __restrict__ out_ve, int E)
{
    extern __shared__ float sm[];
    float* Xs   = sm;                  // [96][PADE]  x transposed (k-major)
    float* Hs   = Xs + 96 * PADE;      // [96][PADE]
    float* Fs   = Hs + 96 * PADE;      // [128][PADE] gated messages
    float* Ws   = Fs + 128 * PADE;     // weight staging (max 96*128)
    float* Wg   = Ws + 12288;          // gate column of Wm2 [96]
    float* B1   = Wg + 96;             // bm1 [96]
    float* Bm   = B1 + 96;             // bm2[1:] [128]
    float* Bev  = Bm + 128;            // be [32]
    float* Ksig = Bev + 32;            // sigmoid gate per edge [128]
    float* Bg   = Ksig + 128;          // bm2[0]

    const int tid  = threadIdx.x;
    const int lane = tid & 31;
    const int warp = tid >> 5;         // 0..7
    const int eBase = blockIdx.x * BE;
    const int e0 = lane * 4;           // edge sub-tile (float4 granularity)

    // --- biases ---
    if (tid < 96)  B1[tid] = bm1[tid];
    if (tid < 128) Bm[tid] = bm2[1 + tid];
    if (tid == 0)  Bg[0]   = bm2[0];
    if (tid < 32)  Bev[tid] = be[tid];

    // --- stage Wm1 [96][96] ---
    {
        const float4* w4 = (const float4*)Wm1;
        float4* s4 = (float4*)Ws;
        for (int i = tid; i < 96 * 96 / 4; i += TPB) s4[i] = w4[i];
    }

    // --- gather X: rows 0..31 vc[src], 32..63 vc[dst], 64..95 ve ---
    for (int e = warp * 16; e < warp * 16 + 16; ++e) {
        int ge  = eBase + e;
        int gec = (ge < E) ? ge : 0;
        int s = src[gec];
        int d = dst[gec];
        Xs[lane * PADE + e]        = vc[(size_t)s * 32 + lane];
        Xs[(32 + lane) * PADE + e] = vc[(size_t)d * 32 + lane];
        Xs[(64 + lane) * PADE + e] = ve[(size_t)gec * 32 + lane];
    }
    __syncthreads();

    // ================= GEMM1: H = relu(X @ Wm1 + b1) =================
    {
        const int o1 = warp * 12;      // 8 warps * 12 = 96 outs
        float acc[12][4];
        #pragma unroll
        for (int j = 0; j < 12; j++)
            #pragma unroll
            for (int i = 0; i < 4; i++) acc[j][i] = 0.f;

        #pragma unroll 2
        for (int k = 0; k < 96; k++) {
            float4 x = *(const float4*)&Xs[k * PADE + e0];
            const float* wr = &Ws[k * 96 + o1];
            #pragma unroll
            for (int j = 0; j < 12; j += 4) {
                float4 w = *(const float4*)(wr + j);
                acc[j+0][0] += w.x * x.x; acc[j+0][1] += w.x * x.y; acc[j+0][2] += w.x * x.z; acc[j+0][3] += w.x * x.w;
                acc[j+1][0] += w.y * x.x; acc[j+1][1] += w.y * x.y; acc[j+1][2] += w.y * x.z; acc[j+1][3] += w.y * x.w;
                acc[j+2][0] += w.z * x.x; acc[j+2][1] += w.z * x.y; acc[j+2][2] += w.z * x.z; acc[j+2][3] += w.z * x.w;
                acc[j+3][0] += w.w * x.x; acc[j+3][1] += w.w * x.y; acc[j+3][2] += w.w * x.z; acc[j+3][3] += w.w * x.w;
            }
        }
        #pragma unroll
        for (int j = 0; j < 12; j++) {
            float b = B1[o1 + j];
            float4 h;
            h.x = fmaxf(acc[j][0] + b, 0.f);
            h.y = fmaxf(acc[j][1] + b, 0.f);
            h.z = fmaxf(acc[j][2] + b, 0.f);
            h.w = fmaxf(acc[j][3] + b, 0.f);
            *(float4*)&Hs[(o1 + j) * PADE + e0] = h;
        }
    }
    __syncthreads();

    // --- stage Wm2: gate column + message block [96][128] ---
    for (int i = tid; i < 96; i += TPB) Wg[i] = Wm2[i * 129];
    for (int i = tid; i < 96 * 128; i += TPB) {
        int k = i >> 7, o = i & 127;
        Ws[i] = Wm2[k * 129 + 1 + o];
    }
    __syncthreads();

    // --- gate: y0 = H @ Wm2[:,0] + b ; ksig = sigmoid(y0) ---
    if (tid < 128) {
        float a = Bg[0];
        #pragma unroll 4
        for (int k = 0; k < 96; k++) a += Hs[k * PADE + tid] * Wg[k];
        Ksig[tid] = 1.f / (1.f + __expf(-a));
    }

    // ================= GEMM2: Y = H @ Wm2[:,1:] ; F = (Y+b)*ksig =================
    {
        const int o2 = warp * 16;      // 8 warps * 16 = 128 outs
        float acc[16][4];
        #pragma unroll
        for (int j = 0; j < 16; j++)
            #pragma unroll
            for (int i = 0; i < 4; i++) acc[j][i] = 0.f;

        #pragma unroll 2
        for (int k = 0; k < 96; k++) {
            float4 h = *(const float4*)&Hs[k * PADE + e0];
            const float* wr = &Ws[k * 128 + o2];
            #pragma unroll
            for (int j = 0; j < 16; j += 4) {
                float4 w = *(const float4*)(wr + j);
                acc[j+0][0] += w.x * h.x; acc[j+0][1] += w.x * h.y; acc[j+0][2] += w.x * h.z; acc[j+0][3] += w.x * h.w;
                acc[j+1][0] += w.y * h.x; acc[j+1][1] += w.y * h.y; acc[j+1][2] += w.y * h.z; acc[j+1][3] += w.y * h.w;
                acc[j+2][0] += w.z * h.x; acc[j+2][1] += w.z * h.y; acc[j+2][2] += w.z * h.z; acc[j+2][3] += w.z * h.w;
                acc[j+3][0] += w.w * h.x; acc[j+3][1] += w.w * h.y; acc[j+3][2] += w.w * h.z; acc[j+3][3] += w.w * h.w;
            }
        }
        __syncthreads();   // Ksig ready; k-loop reads of Ws done before next staging
        float4 ks = *(const float4*)&Ksig[e0];
        #pragma unroll
        for (int j = 0; j < 16; j++) {
            float b = Bm[o2 + j];
            float4 f;
            f.x = (acc[j][0] + b) * ks.x;
            f.y = (acc[j][1] + b) * ks.y;
            f.z = (acc[j][2] + b) * ks.z;
            f.w = (acc[j][3] + b) * ks.w;
            *(float4*)&Fs[(o2 + j) * PADE + e0] = f;
        }
    }
    __syncthreads();

    // --- stage We [160][32] ---
    for (int i = tid; i < 160 * 32 / 4; i += TPB)
        ((float4*)Ws)[i] = ((const float4*)We)[i];
    __syncthreads();

    // ================= GEMM3: out_ve = [F; ve] @ We + be =================
    {
        const int o3 = warp * 4;       // 8 warps * 4 = 32 outs
        float acc[4][4];               // [edge][out]
        #pragma unroll
        for (int j = 0; j < 4; j++)
            #pragma unroll
            for (int i = 0; i < 4; i++) acc[j][i] = 0.f;

        #pragma unroll 4
        for (int k = 0; k < 128; k++) {
            float4 f = *(const float4*)&Fs[k * PADE + e0];
            float4 w = *(const float4*)&Ws[k * 32 + o3];
            acc[0][0] += f.x * w.x; acc[0][1] += f.x * w.y; acc[0][2] += f.x * w.z; acc[0][3] += f.x * w.w;
            acc[1][0] += f.y * w.x; acc[1][1] += f.y * w.y; acc[1][2] += f.y * w.z; acc[1][3] += f.y * w.w;
            acc[2][0] += f.z * w.x; acc[2][1] += f.z * w.y; acc[2][2] += f.z * w.z; acc[2][3] += f.z * w.w;
            acc[3][0] += f.w * w.x; acc[3][1] += f.w * w.y; acc[3][2] += f.w * w.z; acc[3][3] += f.w * w.w;
        }
        #pragma unroll 4
        for (int k = 0; k < 32; k++) {
            float4 v = *(const float4*)&Xs[(64 + k) * PADE + e0];
            float4 w = *(const float4*)&Ws[(128 + k) * 32 + o3];
            acc[0][0] += v.x * w.x; acc[0][1] += v.x * w.y; acc[0][2] += v.x * w.z; acc[0][3] += v.x * w.w;
            acc[1][0] += v.y * w.x; acc[1][1] += v.y * w.y; acc[1][2] += v.y * w.z; acc[1][3] += v.y * w.w;
            acc[2][0] += v.z * w.x; acc[2][1] += v.z * w.y; acc[2][2] += v.z * w.z; acc[2][3] += v.z * w.w;
            acc[3][0] += v.w * w.x; acc[3][1] += v.w * w.y; acc[3][2] += v.w * w.z; acc[3][3] += v.w * w.w;
        }
        float4 b = *(const float4*)&Bev[o3];
        #pragma unroll
        for (int j = 0; j < 4; j++) {
            int ge = eBase + e0 + j;
            if (ge < E) {
                float4 r;
                r.x = acc[j][0] + b.x;
                r.y = acc[j][1] + b.y;
                r.z = acc[j][2] + b.z;
                r.w = acc[j][3] + b.w;
                *(float4*)&out_ve[(size_t)ge * 32 + o3] = r;
            }
        }
    }

    // ================= scatter: atomics per (edge, channel) =================
    for (int e = warp * 16; e < warp * 16 + 16; ++e) {
        int ge = eBase + e;
        if (ge >= E) break;
        int d = dst[ge];
        float v1 = Fs[lane * PADE + e];
        float v2 = Fs[(32 + lane) * PADE + e];
        float v3 = Fs[(64 + lane) * PADE + e];
        float v4 = Fs[(96 + lane) * PADE + e];
        atomicAdd(&g_s1[d * 32 + lane], v1);
        atomicMax(&g_m2[d * 32 + lane], encf(v2));
        atomicMin(&g_m3[d * 32 + lane], encf(v3));
        atomicAdd(&g_m4[d * 32 + lane], v4);
        if (lane == 0) atomicAdd(&g_deg[d], 1.0f);
    }
}

// ================= node update: out_vc = [vc,s1,m2,m3,m4] @ Wr + br =================
__global__ __launch_bounds__(256)
void node_kernel(const float* __restrict__ vc, const float* __restrict__ Wr,
                 const float* __restrict__ br, float* __restrict__ out_vc, int N)
{
    __shared__ float Wrs[160 * 32];
    __shared__ float brs[32];
    const int tid = threadIdx.x, lane = tid & 31, warp = tid >> 5;
    for (int i = tid; i < 160 * 32 / 4; i += 256)
        ((float4*)Wrs)[i] = ((const float4*)Wr)[i];
    if (tid < 32) brs[tid] = br[tid];
    __syncthreads();

    int n = blockIdx.x * 8 + warp;
    if (n >= N) return;

    float deg = g_deg[n];
    bool has = deg > 0.f;
    float xsv[5];
    xsv[0] = vc[(size_t)n * 32 + lane];
    xsv[1] = g_s1[n * 32 + lane];
    xsv[2] = has ? decf(g_m2[n * 32 + lane]) : 0.f;
    xsv[3] = has ? decf(g_m3[n * 32 + lane]) : 0.f;
    xsv[4] = g_m4[n * 32 + lane] / fmaxf(deg, 1.f);

    float acc = brs[lane];
    #pragma unroll
    for (int p = 0; p < 5; p++) {
        #pragma unroll
        for (int k = 0; k < 32; k++) {
            float xv = __shfl_sync(0xffffffffu, xsv[p], k);
            acc += xv * Wrs[(p * 32 + k) * 32 + lane];
        }
    }
    out_vc[(size_t)n * 32 + lane] = acc;
}

extern "C" void kernel_launch(void* const* d_in, const int* in_sizes, int n_in,
                              void* d_out, int out_size)
{
    const float* vc  = (const float*)d_in[0];
    const float* ve  = (const float*)d_in[1];
    const int*   src = (const int*)d_in[2];
    const int*   dst = (const int*)d_in[3];
    const float* Wm1 = (const float*)d_in[4];
    const float* bm1 = (const float*)d_in[5];
    const float* Wm2 = (const float*)d_in[6];
    const float* bm2 = (const float*)d_in[7];
    const float* Wr  = (const float*)d_in[8];
    const float* br  = (const float*)d_in[9];
    const float* We  = (const float*)d_in[10];
    const float* be  = (const float*)d_in[11];

    int N = in_sizes[0] / 32;
    int E = in_sizes[2];

    float* out_vc = (float*)d_out;
    float* out_ve = out_vc + (size_t)N * 32;

    const size_t smem_bytes = (size_t)SMEM_FLOATS * sizeof(float);
    cudaFuncSetAttribute(edge_kernel, cudaFuncAttributeMaxDynamicSharedMemorySize,
                         (int)smem_bytes);

    init_kernel<<<(N * 32 + 255) / 256, 256>>>(N);
    edge_kernel<<<(E + BE - 1) / BE, TPB, smem_bytes>>>(
        vc, ve, src, dst, Wm1, bm1, Wm2, bm2, We, be, out_ve, E);
    node_kernel<<<(N + 7) / 8, 256>>>(vc, Wr, br, out_vc, N);
}

// round 4
// speedup vs baseline: 1.3525x; 1.3525x over previous
#include <cuda_runtime.h>
#include <cuda_bf16.h>
#include <cstdint>

// ---------------------------------------------------------------------------
// GSMP_4879082848655 — mma.sync bf16-split edge pipeline (sm_103 base ISA)
//   D = Ah*Bh + Al*Bh + Ah*Bl  (hi/lo bf16 split ~ fp32 accuracy)
//   GEMM1: X[128x96]  @ W1 -> H[128x96] (relu)
//   GEMM2: H[128x96]  @ [W2msg|gate] -> D2[128x136] (col128 = gate)
//   GEMM3: [F|ve][128x160] @ We -> out_ve[128x32]
// Warp-owned 16-row M-tiles: phases are warp-local after the gather barrier.
// ---------------------------------------------------------------------------

#define MAXN 100000
#define BE   128
#define TPB  256

#define SA 168   // A-buffer col stride (bf16 elems): 84 words, conflict-free
#define SH 104   // H-buffer col stride: 52 words, conflict-free

// smem byte offsets
#define O_AHI 0
#define O_ALO 43008              // 128*168*2
#define O_HHI 86016
#define O_HLO 112640             // +128*104*2
#define O_SK  139264
#define O_DST 139776
#define SMEMB 140288

// frag tables: G1: 12nt*6ks*2hl=144, G2: 17*6*2=204, G3: 4*10*2=80
__device__ uint2 gF1[144 * 32];
__device__ uint2 gF2[204 * 32];
__device__ uint2 gF3[80 * 32];

__device__ float    g_s1[MAXN * 32];
__device__ float    g_m4[MAXN * 32];
__device__ unsigned g_m2[MAXN * 32];
__device__ unsigned g_m3[MAXN * 32];
__device__ float    g_deg[MAXN];

// ---------------- helpers ----------------
__device__ __forceinline__ unsigned encf(float f) {
    unsigned u = __float_as_uint(f);
    return (u & 0x80000000u) ? ~u : (u | 0x80000000u);
}
__device__ __forceinline__ float decf(unsigned u) {
    u = (u & 0x80000000u) ? (u & 0x7FFFFFFFu) : ~u;
    return __uint_as_float(u);
}
__device__ __forceinline__ void split2(float a, float b, uint32_t& hi, uint32_t& lo) {
    __nv_bfloat16 ah = __float2bfloat16_rn(a), bh = __float2bfloat16_rn(b);
    __nv_bfloat162 hv; hv.x = ah; hv.y = bh;
    __nv_bfloat162 lv = __floats2bfloat162_rn(a - __bfloat162float(ah),
                                              b - __bfloat162float(bh));
    hi = *reinterpret_cast<uint32_t*>(&hv);
    lo = *reinterpret_cast<uint32_t*>(&lv);
}
__device__ __forceinline__ void redadd2(float* p, float a, float b) {
    asm volatile("red.global.add.v2.f32 [%0], {%1,%2};" :: "l"(p), "f"(a), "f"(b) : "memory");
}
__device__ __forceinline__ void redadd1(float* p, float v) {
    asm volatile("red.global.add.f32 [%0], %1;" :: "l"(p), "f"(v) : "memory");
}
__device__ __forceinline__ void redmaxu(unsigned* p, unsigned v) {
    asm volatile("red.global.max.u32 [%0], %1;" :: "l"(p), "r"(v) : "memory");
}
__device__ __forceinline__ void redminu(unsigned* p, unsigned v) {
    asm volatile("red.global.min.u32 [%0], %1;" :: "l"(p), "r"(v) : "memory");
}
__device__ __forceinline__ void mma16816(float* c, const uint32_t* a, uint2 b) {
    asm volatile(
        "mma.sync.aligned.m16n8k16.row.col.f32.bf16.bf16.f32 "
        "{%0,%1,%2,%3}, {%4,%5,%6,%7}, {%8,%9}, {%0,%1,%2,%3};"
        : "+f"(c[0]), "+f"(c[1]), "+f"(c[2]), "+f"(c[3])
        : "r"(a[0]), "r"(a[1]), "r"(a[2]), "r"(a[3]), "r"(b.x), "r"(b.y));
}

// ---------------- prep: build B fragments in mma layout ----------------
// frag (nt, ks, hl); lane: g=lane>>2 (n offset), tig=lane&3 (k offset)
// reg0 = bf16x2( w(k0,n), w(k0+1,n) ), reg1 = bf16x2( w(k0+8,n), w(k0+9,n) )
__device__ __forceinline__ uint32_t pack_hl(float w0, float w1, int hl) {
    __nv_bfloat16 h0 = __float2bfloat16_rn(w0), h1 = __float2bfloat16_rn(w1);
    if (hl) {
        h0 = __float2bfloat16_rn(w0 - __bfloat162float(h0));
        h1 = __float2bfloat16_rn(w1 - __bfloat162float(h1));
    }
    __nv_bfloat162 v; v.x = h0; v.y = h1;
    return *reinterpret_cast<uint32_t*>(&v);
}

__global__ void prep_kernel(const float* __restrict__ Wm1, const float* __restrict__ Wm2,
                            const float* __restrict__ We) {
    int t = blockIdx.x * blockDim.x + threadIdx.x;
    if (t >= 428 * 32) return;
    int lane = t & 31, f = t >> 5;
    int g = lane >> 2, tig = lane & 3;

    if (f < 144) {                     // GEMM1: W1[k<96][n<96]
        int hl = f & 1, q = f >> 1, ks = q % 6, nt = q / 6;
        int n = nt * 8 + g, k0 = ks * 16 + tig * 2;
        float w00 = Wm1[k0 * 96 + n],       w01 = Wm1[(k0 + 1) * 96 + n];
        float w10 = Wm1[(k0 + 8) * 96 + n], w11 = Wm1[(k0 + 9) * 96 + n];
        gF1[f * 32 + lane] = make_uint2(pack_hl(w00, w01, hl), pack_hl(w10, w11, hl));
    } else if (f < 348) {              // GEMM2: [W2msg | gate | 0][k<96][n<136]
        int f2 = f - 144, hl = f2 & 1, q = f2 >> 1, ks = q % 6, nt = q / 6;
        int n = nt * 8 + g, k0 = ks * 16 + tig * 2;
        float w[4];
        #pragma unroll
        for (int i = 0; i < 4; i++) {
            int k = k0 + (i >> 1) * 8 + (i & 1);
            if (n < 128)       w[i] = Wm2[k * 129 + 1 + n];
            else if (n == 128) w[i] = Wm2[k * 129];
            else               w[i] = 0.f;
        }
        gF2[f2 * 32 + lane] = make_uint2(pack_hl(w[0], w[1], hl), pack_hl(w[2], w[3], hl));
    } else {                           // GEMM3: We[k<160][n<32]
        int f3 = f - 348, hl = f3 & 1, q = f3 >> 1, ks = q % 10, nt = q / 10;
        int n = nt * 8 + g, k0 = ks * 16 + tig * 2;
        float w00 = We[k0 * 32 + n],       w01 = We[(k0 + 1) * 32 + n];
        float w10 = We[(k0 + 8) * 32 + n], w11 = We[(k0 + 9) * 32 + n];
        gF3[f3 * 32 + lane] = make_uint2(pack_hl(w00, w01, hl), pack_hl(w10, w11, hl));
    }
}

__global__ void init_kernel(int N) {
    int i = blockIdx.x * blockDim.x + threadIdx.x;
    int tot = N * 8;
    if (i < tot) {
        float4 z = make_float4(0.f, 0.f, 0.f, 0.f);
        ((float4*)g_s1)[i] = z;
        ((float4*)g_m4)[i] = z;
        ((uint4*)g_m2)[i] = make_uint4(0u, 0u, 0u, 0u);
        ((uint4*)g_m3)[i] = make_uint4(~0u, ~0u, ~0u, ~0u);
    }
    if (i < N) g_deg[i] = 0.f;
}

// ---------------- edge kernel ----------------
__global__ __launch_bounds__(TPB, 1)
void edge_kernel(const float* __restrict__ vc, const float* __restrict__ ve,
                 const int* __restrict__ src, const int* __restrict__ dst,
                 const float* __restrict__ bm1, const float* __restrict__ bm2,
                 const float* __restrict__ be, float* __restrict__ out_ve, int E)
{
    extern __shared__ char sm[];
    float* sK  = (float*)(sm + O_SK);
    int*  sDst = (int*)(sm + O_DST);

    const int tid  = threadIdx.x;
    const int lane = tid & 31;
    const int wid  = tid >> 5;
    const int g    = lane >> 2;
    const int tig  = lane & 3;
    const int eBase = blockIdx.x * BE;

    // ---- gather: row-major bf16 hi/lo ----
    {
        int e = tid >> 1, half = tid & 1;
        int ge = eBase + e;
        int gec = (ge < E) ? ge : (E - 1);
        int sN = src[gec], dN = dst[gec];
        if (half == 0) sDst[e] = dN;
        const float4* vs = (const float4*)(vc + (size_t)sN * 32);
        const float4* vd = (const float4*)(vc + (size_t)dN * 32);
        const float4* vv = (const float4*)(ve + (size_t)gec * 32);

        auto put4 = [&](int col, float4 v) {
            uint32_t h0, l0, h1, l1;
            split2(v.x, v.y, h0, l0);
            split2(v.z, v.w, h1, l1);
            int idx = (e * SA + col) * 2;
            *(uint2*)(sm + O_AHI + idx) = make_uint2(h0, h1);
            *(uint2*)(sm + O_ALO + idx) = make_uint2(l0, l1);
        };
        if (half == 0) {
            #pragma unroll
            for (int q = 0; q < 8; q++) put4(q * 4, vs[q]);
            #pragma unroll
            for (int q = 0; q < 4; q++) put4(32 + q * 4, vd[q]);
        } else {
            #pragma unroll
            for (int q = 0; q < 8; q++) {
                float4 v = vv[q];
                put4(64 + q * 4, v);
                put4(128 + q * 4, v);   // second copy for GEMM3
            }
            #pragma unroll
            for (int q = 0; q < 4; q++) put4(48 + q * 4, vd[4 + q]);
        }
    }
    __syncthreads();

    const int r0 = wid * 16 + g;   // warp-owned rows: r0 and r0+8
    const int ge0 = eBase + r0, ge1 = ge0 + 8;
    const bool ok0 = ge0 < E, ok1 = ge1 < E;

    // ================= GEMM1 =================
    {
        float c[12][4];
        #pragma unroll
        for (int nt = 0; nt < 12; nt++)
            #pragma unroll
            for (int i = 0; i < 4; i++) c[nt][i] = 0.f;

        #pragma unroll
        for (int ks = 0; ks < 6; ks++) {
            int b0 = (r0 * SA + ks * 16 + tig * 2) * 2;
            int b1 = ((r0 + 8) * SA + ks * 16 + tig * 2) * 2;
            uint32_t Ah[4], Al[4];
            Ah[0] = *(uint32_t*)(sm + O_AHI + b0);
            Ah[1] = *(uint32_t*)(sm + O_AHI + b1);
            Ah[2] = *(uint32_t*)(sm + O_AHI + b0 + 16);
            Ah[3] = *(uint32_t*)(sm + O_AHI + b1 + 16);
            Al[0] = *(uint32_t*)(sm + O_ALO + b0);
            Al[1] = *(uint32_t*)(sm + O_ALO + b1);
            Al[2] = *(uint32_t*)(sm + O_ALO + b0 + 16);
            Al[3] = *(uint32_t*)(sm + O_ALO + b1 + 16);
            #pragma unroll
            for (int nt = 0; nt < 12; nt++) {
                uint2 bh = gF1[((nt * 6 + ks) * 2 + 0) * 32 + lane];
                uint2 bl = gF1[((nt * 6 + ks) * 2 + 1) * 32 + lane];
                mma16816(c[nt], Ah, bh);
                mma16816(c[nt], Al, bh);
                mma16816(c[nt], Ah, bl);
            }
        }
        // epi1: H = relu(c + b1) -> bufH
        #pragma unroll
        for (int nt = 0; nt < 12; nt++) {
            int col = nt * 8 + tig * 2;
            float b0v = __ldg(&bm1[col]), b1v = __ldg(&bm1[col + 1]);
            float h00 = fmaxf(c[nt][0] + b0v, 0.f), h01 = fmaxf(c[nt][1] + b1v, 0.f);
            float h10 = fmaxf(c[nt][2] + b0v, 0.f), h11 = fmaxf(c[nt][3] + b1v, 0.f);
            uint32_t hi, lo;
            split2(h00, h01, hi, lo);
            int i0 = (r0 * SH + col) * 2;
            *(uint32_t*)(sm + O_HHI + i0) = hi;
            *(uint32_t*)(sm + O_HLO + i0) = lo;
            split2(h10, h11, hi, lo);
            int i1 = ((r0 + 8) * SH + col) * 2;
            *(uint32_t*)(sm + O_HHI + i1) = hi;
            *(uint32_t*)(sm + O_HLO + i1) = lo;
        }
    }
    __syncwarp();

    // ================= GEMM2 =================
    {
        float c[17][4];
        #pragma unroll
        for (int nt = 0; nt < 17; nt++)
            #pragma unroll
            for (int i = 0; i < 4; i++) c[nt][i] = 0.f;

        #pragma unroll
        for (int ks = 0; ks < 6; ks++) {
            int b0 = (r0 * SH + ks * 16 + tig * 2) * 2;
            int b1 = ((r0 + 8) * SH + ks * 16 + tig * 2) * 2;
            uint32_t Ah[4], Al[4];
            Ah[0] = *(uint32_t*)(sm + O_HHI + b0);
            Ah[1] = *(uint32_t*)(sm + O_HHI + b1);
            Ah[2] = *(uint32_t*)(sm + O_HHI + b0 + 16);
            Ah[3] = *(uint32_t*)(sm + O_HHI + b1 + 16);
            Al[0] = *(uint32_t*)(sm + O_HLO + b0);
            Al[1] = *(uint32_t*)(sm + O_HLO + b1);
            Al[2] = *(uint32_t*)(sm + O_HLO + b0 + 16);
            Al[3] = *(uint32_t*)(sm + O_HLO + b1 + 16);
            #pragma unroll
            for (int nt = 0; nt < 17; nt++) {
                uint2 bh = gF2[((nt * 6 + ks) * 2 + 0) * 32 + lane];
                uint2 bl = gF2[((nt * 6 + ks) * 2 + 1) * 32 + lane];
                mma16816(c[nt], Ah, bh);
                mma16816(c[nt], Al, bh);
                mma16816(c[nt], Ah, bl);
            }
        }
        // gate (col 128 = nt16, tig==0, c0/c2)
        if (tig == 0) {
            float b0v = __ldg(&bm2[0]);
            sK[r0]     = 1.f / (1.f + __expf(-(c[16][0] + b0v)));
            sK[r0 + 8] = 1.f / (1.f + __expf(-(c[16][2] + b0v)));
        }
        __syncwarp();
        float kg0 = sK[r0], kg1 = sK[r0 + 8];
        int d0 = sDst[r0], d1 = sDst[r0 + 8];

        #pragma unroll
        for (int nt = 0; nt < 16; nt++) {
            int col = nt * 8 + tig * 2;
            float b0v = __ldg(&bm2[1 + col]), b1v = __ldg(&bm2[2 + col]);
            float f00 = (c[nt][0] + b0v) * kg0, f01 = (c[nt][1] + b1v) * kg0;
            float f10 = (c[nt][2] + b0v) * kg1, f11 = (c[nt][3] + b1v) * kg1;
            // F -> bufA (cols 0..127) for GEMM3
            uint32_t hi, lo;
            split2(f00, f01, hi, lo);
            int i0 = (r0 * SA + col) * 2;
            *(uint32_t*)(sm + O_AHI + i0) = hi;
            *(uint32_t*)(sm + O_ALO + i0) = lo;
            split2(f10, f11, hi, lo);
            int i1 = ((r0 + 8) * SA + col) * 2;
            *(uint32_t*)(sm + O_AHI + i1) = hi;
            *(uint32_t*)(sm + O_ALO + i1) = lo;
            // scatter
            if (nt < 4) {
                if (ok0) redadd2(&g_s1[(size_t)d0 * 32 + col], f00, f01);
                if (ok1) redadd2(&g_s1[(size_t)d1 * 32 + col], f10, f11);
            } else if (nt < 8) {
                int cc = col - 32;
                if (ok0) { redmaxu(&g_m2[(size_t)d0 * 32 + cc], encf(f00));
                           redmaxu(&g_m2[(size_t)d0 * 32 + cc + 1], encf(f01)); }
                if (ok1) { redmaxu(&g_m2[(size_t)d1 * 32 + cc], encf(f10));
                           redmaxu(&g_m2[(size_t)d1 * 32 + cc + 1], encf(f11)); }
            } else if (nt < 12) {
                int cc = col - 64;
                if (ok0) { redminu(&g_m3[(size_t)d0 * 32 + cc], encf(f00));
                           redminu(&g_m3[(size_t)d0 * 32 + cc + 1], encf(f01)); }
                if (ok1) { redminu(&g_m3[(size_t)d1 * 32 + cc], encf(f10));
                           redminu(&g_m3[(size_t)d1 * 32 + cc + 1], encf(f11)); }
            } else {
                int cc = col - 96;
                if (ok0) redadd2(&g_m4[(size_t)d0 * 32 + cc], f00, f01);
                if (ok1) redadd2(&g_m4[(size_t)d1 * 32 + cc], f10, f11);
            }
        }
        if (tig == 0) {
            if (ok0) redadd1(&g_deg[d0], 1.f);
            if (ok1) redadd1(&g_deg[d1], 1.f);
        }
    }
    __syncwarp();

    // ================= GEMM3 =================
    {
        float c[4][4];
        #pragma unroll
        for (int nt = 0; nt < 4; nt++)
            #pragma unroll
            for (int i = 0; i < 4; i++) c[nt][i] = 0.f;

        #pragma unroll
        for (int ks = 0; ks < 10; ks++) {
            int b0 = (r0 * SA + ks * 16 + tig * 2) * 2;
            int b1 = ((r0 + 8) * SA + ks * 16 + tig * 2) * 2;
            uint32_t Ah[4], Al[4];
            Ah[0] = *(uint32_t*)(sm + O_AHI + b0);
            Ah[1] = *(uint32_t*)(sm + O_AHI + b1);
            Ah[2] = *(uint32_t*)(sm + O_AHI + b0 + 16);
            Ah[3] = *(uint32_t*)(sm + O_AHI + b1 + 16);
            Al[0] = *(uint32_t*)(sm + O_ALO + b0);
            Al[1] = *(uint32_t*)(sm + O_ALO + b1);
            Al[2] = *(uint32_t*)(sm + O_ALO + b0 + 16);
            Al[3] = *(uint32_t*)(sm + O_ALO + b1 + 16);
            #pragma unroll
            for (int nt = 0; nt < 4; nt++) {
                uint2 bh = gF3[((nt * 10 + ks) * 2 + 0) * 32 + lane];
                uint2 bl = gF3[((nt * 10 + ks) * 2 + 1) * 32 + lane];
                mma16816(c[nt], Ah, bh);
                mma16816(c[nt], Al, bh);
                mma16816(c[nt], Ah, bl);
            }
        }
        #pragma unroll
        for (int nt = 0; nt < 4; nt++) {
            int col = nt * 8 + tig * 2;
            float b0v = __ldg(&be[col]), b1v = __ldg(&be[col + 1]);
            if (ok0) {
                float2 r = make_float2(c[nt][0] + b0v, c[nt][1] + b1v);
                *(float2*)(out_ve + (size_t)ge0 * 32 + col) = r;
            }
            if (ok1) {
                float2 r = make_float2(c[nt][2] + b0v, c[nt][3] + b1v);
                *(float2*)(out_ve + (size_t)ge1 * 32 + col) = r;
            }
        }
    }
}

// ================= node update =================
__global__ __launch_bounds__(256)
void node_kernel(const float* __restrict__ vc, const float* __restrict__ Wr,
                 const float* __restrict__ br, float* __restrict__ out_vc, int N)
{
    __shared__ float Wrs[160 * 32];
    __shared__ float brs[32];
    const int tid = threadIdx.x, lane = tid & 31, warp = tid >> 5;
    for (int i = tid; i < 160 * 32 / 4; i += 256)
        ((float4*)Wrs)[i] = ((const float4*)Wr)[i];
    if (tid < 32) brs[tid] = br[tid];
    __syncthreads();

    int n = blockIdx.x * 8 + warp;
    if (n >= N) return;

    float deg = g_deg[n];
    bool has = deg > 0.f;
    float xsv[5];
    xsv[0] = vc[(size_t)n * 32 + lane];
    xsv[1] = g_s1[n * 32 + lane];
    xsv[2] = has ? decf(g_m2[n * 32 + lane]) : 0.f;
    xsv[3] = has ? decf(g_m3[n * 32 + lane]) : 0.f;
    xsv[4] = g_m4[n * 32 + lane] / fmaxf(deg, 1.f);

    float acc = brs[lane];
    #pragma unroll
    for (int p = 0; p < 5; p++) {
        #pragma unroll
        for (int k = 0; k < 32; k++) {
            float xv = __shfl_sync(0xffffffffu, xsv[p], k);
            acc += xv * Wrs[(p * 32 + k) * 32 + lane];
        }
    }
    out_vc[(size_t)n * 32 + lane] = acc;
}

extern "C" void kernel_launch(void* const* d_in, const int* in_sizes, int n_in,
                              void* d_out, int out_size)
{
    const float* vc  = (const float*)d_in[0];
    const float* ve  = (const float*)d_in[1];
    const int*   src = (const int*)d_in[2];
    const int*   dst = (const int*)d_in[3];
    const float* Wm1 = (const float*)d_in[4];
    const float* bm1 = (const float*)d_in[5];
    const float* Wm2 = (const float*)d_in[6];
    const float* bm2 = (const float*)d_in[7];
    const float* Wr  = (const float*)d_in[8];
    const float* br  = (const float*)d_in[9];
    const float* We  = (const float*)d_in[10];
    const float* be  = (const float*)d_in[11];

    int N = in_sizes[0] / 32;
    int E = in_sizes[2];

    float* out_vc = (float*)d_out;
    float* out_ve = out_vc + (size_t)N * 32;

    cudaFuncSetAttribute(edge_kernel, cudaFuncAttributeMaxDynamicSharedMemorySize, SMEMB);

    prep_kernel<<<(428 * 32 + 255) / 256, 256>>>(Wm1, Wm2, We);
    init_kernel<<<(N * 8 + 255) / 256, 256>>>(N);
    edge_kernel<<<(E + BE - 1) / BE, TPB, SMEMB>>>(
        vc, ve, src, dst, bm1, bm2, be, out_ve, E);
    node_kernel<<<(N + 7) / 8, 256>>>(vc, Wr, br, out_vc, N);
}

// round 5
// speedup vs baseline: 1.7053x; 1.2609x over previous
#include <cuda_runtime.h>
#include <cuda_bf16.h>
#include <cstdint>

// ---------------------------------------------------------------------------
// GSMP_4879082848655 — mma.sync bf16-split pipeline, smem-staged fragments
// ---------------------------------------------------------------------------

#define MAXN 100000
#define BE   128
#define TPB  256

#define SA 168   // A-buffer col stride (bf16): 84 words, conflict-free
#define SH 104   // H-buffer col stride

// edge kernel smem byte offsets
#define O_AHI 0
#define O_ALO 43008              // 128*168*2
#define O_HHI 86016
#define O_HLO 112640
#define O_F12 139264             // 52224 B (F2 = 204*32*8; F1 fits inside)
#define O_F3  191488             // 20480 B (80*32*8)
#define O_SK  211968
#define O_DST 212480
#define SMEMB 212992

// node kernel smem
#define ON_AHI 0
#define ON_ALO 43008
#define NSMEMB 86016

// frag tables: G1: 12nt*6ks*2 = 144, G2: 17*6*2 = 204, G3/Gr: 4*10*2 = 80
__device__ uint2 gF1[144 * 32];
__device__ uint2 gF2[204 * 32];
__device__ uint2 gF3[80 * 32];
__device__ uint2 gFr[80 * 32];

__device__ float    g_s1[MAXN * 32];
__device__ float    g_m4[MAXN * 32];
__device__ unsigned g_m2[MAXN * 32];
__device__ unsigned g_m3[MAXN * 32];
__device__ float    g_deg[MAXN];

// ---------------- helpers ----------------
__device__ __forceinline__ unsigned encf(float f) {
    unsigned u = __float_as_uint(f);
    return (u & 0x80000000u) ? ~u : (u | 0x80000000u);
}
__device__ __forceinline__ float decf(unsigned u) {
    u = (u & 0x80000000u) ? (u & 0x7FFFFFFFu) : ~u;
    return __uint_as_float(u);
}
__device__ __forceinline__ void split2(float a, float b, uint32_t& hi, uint32_t& lo) {
    __nv_bfloat16 ah = __float2bfloat16_rn(a), bh = __float2bfloat16_rn(b);
    __nv_bfloat162 hv; hv.x = ah; hv.y = bh;
    __nv_bfloat162 lv = __floats2bfloat162_rn(a - __bfloat162float(ah),
                                              b - __bfloat162float(bh));
    hi = *reinterpret_cast<uint32_t*>(&hv);
    lo = *reinterpret_cast<uint32_t*>(&lv);
}
__device__ __forceinline__ void redadd2(float* p, float a, float b) {
    asm volatile("red.global.add.v2.f32 [%0], {%1,%2};" :: "l"(p), "f"(a), "f"(b) : "memory");
}
__device__ __forceinline__ void redadd1(float* p, float v) {
    asm volatile("red.global.add.f32 [%0], %1;" :: "l"(p), "f"(v) : "memory");
}
__device__ __forceinline__ void redmaxu(unsigned* p, unsigned v) {
    asm volatile("red.global.max.u32 [%0], %1;" :: "l"(p), "r"(v) : "memory");
}
__device__ __forceinline__ void redminu(unsigned* p, unsigned v) {
    asm volatile("red.global.min.u32 [%0], %1;" :: "l"(p), "r"(v) : "memory");
}
__device__ __forceinline__ void mma16816(float* c, const uint32_t* a, uint2 b) {
    asm volatile(
        "mma.sync.aligned.m16n8k16.row.col.f32.bf16.bf16.f32 "
        "{%0,%1,%2,%3}, {%4,%5,%6,%7}, {%8,%9}, {%0,%1,%2,%3};"
        : "+f"(c[0]), "+f"(c[1]), "+f"(c[2]), "+f"(c[3])
        : "r"(a[0]), "r"(a[1]), "r"(a[2]), "r"(a[3]), "r"(b.x), "r"(b.y));
}

__device__ __forceinline__ uint32_t pack_hl(float w0, float w1, int hl) {
    __nv_bfloat16 h0 = __float2bfloat16_rn(w0), h1 = __float2bfloat16_rn(w1);
    if (hl) {
        h0 = __float2bfloat16_rn(w0 - __bfloat162float(h0));
        h1 = __float2bfloat16_rn(w1 - __bfloat162float(h1));
    }
    __nv_bfloat162 v; v.x = h0; v.y = h1;
    return *reinterpret_cast<uint32_t*>(&v);
}

// ---------------- prep: B fragments in mma layout ----------------
__global__ void prep_kernel(const float* __restrict__ Wm1, const float* __restrict__ Wm2,
                            const float* __restrict__ We,  const float* __restrict__ Wr) {
    int t = blockIdx.x * blockDim.x + threadIdx.x;
    if (t >= 508 * 32) return;
    int lane = t & 31, f = t >> 5;
    int g = lane >> 2, tig = lane & 3;

    if (f < 144) {                     // GEMM1: W1[k<96][n<96]
        int hl = f & 1, q = f >> 1, ks = q % 6, nt = q / 6;
        int n = nt * 8 + g, k0 = ks * 16 + tig * 2;
        float w00 = Wm1[k0 * 96 + n],       w01 = Wm1[(k0 + 1) * 96 + n];
        float w10 = Wm1[(k0 + 8) * 96 + n], w11 = Wm1[(k0 + 9) * 96 + n];
        gF1[f * 32 + lane] = make_uint2(pack_hl(w00, w01, hl), pack_hl(w10, w11, hl));
    } else if (f < 348) {              // GEMM2: [W2msg | gate | 0][k<96][n<136]
        int f2 = f - 144, hl = f2 & 1, q = f2 >> 1, ks = q % 6, nt = q / 6;
        int n = nt * 8 + g, k0 = ks * 16 + tig * 2;
        float w[4];
        #pragma unroll
        for (int i = 0; i < 4; i++) {
            int k = k0 + (i >> 1) * 8 + (i & 1);
            if (n < 128)       w[i] = Wm2[k * 129 + 1 + n];
            else if (n == 128) w[i] = Wm2[k * 129];
            else               w[i] = 0.f;
        }
        gF2[f2 * 32 + lane] = make_uint2(pack_hl(w[0], w[1], hl), pack_hl(w[2], w[3], hl));
    } else if (f < 428) {              // GEMM3: We[k<160][n<32]
        int f3 = f - 348, hl = f3 & 1, q = f3 >> 1, ks = q % 10, nt = q / 10;
        int n = nt * 8 + g, k0 = ks * 16 + tig * 2;
        float w00 = We[k0 * 32 + n],       w01 = We[(k0 + 1) * 32 + n];
        float w10 = We[(k0 + 8) * 32 + n], w11 = We[(k0 + 9) * 32 + n];
        gF3[f3 * 32 + lane] = make_uint2(pack_hl(w00, w01, hl), pack_hl(w10, w11, hl));
    } else {                           // node GEMM: Wr[k<160][n<32]
        int f4 = f - 428, hl = f4 & 1, q = f4 >> 1, ks = q % 10, nt = q / 10;
        int n = nt * 8 + g, k0 = ks * 16 + tig * 2;
        float w00 = Wr[k0 * 32 + n],       w01 = Wr[(k0 + 1) * 32 + n];
        float w10 = Wr[(k0 + 8) * 32 + n], w11 = Wr[(k0 + 9) * 32 + n];
        gFr[f4 * 32 + lane] = make_uint2(pack_hl(w00, w01, hl), pack_hl(w10, w11, hl));
    }
}

__global__ void init_kernel(int N) {
    int i = blockIdx.x * blockDim.x + threadIdx.x;
    int tot = N * 8;
    if (i < tot) {
        float4 z = make_float4(0.f, 0.f, 0.f, 0.f);
        ((float4*)g_s1)[i] = z;
        ((float4*)g_m4)[i] = z;
        ((uint4*)g_m2)[i] = make_uint4(0u, 0u, 0u, 0u);
        ((uint4*)g_m3)[i] = make_uint4(~0u, ~0u, ~0u, ~0u);
    }
    if (i < N) g_deg[i] = 0.f;
}

// ---------------- edge kernel ----------------
__global__ __launch_bounds__(TPB, 1)
void edge_kernel(const float* __restrict__ vc, const float* __restrict__ ve,
                 const int* __restrict__ src, const int* __restrict__ dst,
                 const float* __restrict__ bm1, const float* __restrict__ bm2,
                 const float* __restrict__ be, float* __restrict__ out_ve, int E)
{
    extern __shared__ char sm[];
    float* sK   = (float*)(sm + O_SK);
    int*  sDst  = (int*)(sm + O_DST);
    uint2* sF12 = (uint2*)(sm + O_F12);
    uint2* sF3  = (uint2*)(sm + O_F3);

    const int tid  = threadIdx.x;
    const int lane = tid & 31;
    const int wid  = tid >> 5;
    const int g    = lane >> 2;
    const int tig  = lane & 3;
    const int eBase = blockIdx.x * BE;

    // ---- stage F1 + F3 frags ----
    for (int i = tid; i < 144 * 32; i += TPB) sF12[i] = gF1[i];
    for (int i = tid; i < 80 * 32; i += TPB)  sF3[i]  = gF3[i];

    // ---- gather: row-major bf16 hi/lo ----
    {
        int e = tid >> 1, half = tid & 1;
        int ge = eBase + e;
        int gec = (ge < E) ? ge : (E - 1);
        int sN = src[gec], dN = dst[gec];
        if (half == 0) sDst[e] = dN;
        const float4* vs = (const float4*)(vc + (size_t)sN * 32);
        const float4* vd = (const float4*)(vc + (size_t)dN * 32);
        const float4* vv = (const float4*)(ve + (size_t)gec * 32);

        auto put4 = [&](int col, float4 v) {
            uint32_t h0, l0, h1, l1;
            split2(v.x, v.y, h0, l0);
            split2(v.z, v.w, h1, l1);
            int idx = (e * SA + col) * 2;
            *(uint2*)(sm + O_AHI + idx) = make_uint2(h0, h1);
            *(uint2*)(sm + O_ALO + idx) = make_uint2(l0, l1);
        };
        if (half == 0) {
            #pragma unroll
            for (int q = 0; q < 8; q++) put4(q * 4, vs[q]);
            #pragma unroll
            for (int q = 0; q < 4; q++) put4(32 + q * 4, vd[q]);
        } else {
            #pragma unroll
            for (int q = 0; q < 8; q++) {
                float4 v = vv[q];
                put4(64 + q * 4, v);
                put4(128 + q * 4, v);   // second copy for GEMM3
            }
            #pragma unroll
            for (int q = 0; q < 4; q++) put4(48 + q * 4, vd[4 + q]);
        }
    }
    __syncthreads();

    const int r0 = wid * 16 + g;
    const int ge0 = eBase + r0, ge1 = ge0 + 8;
    const bool ok0 = ge0 < E, ok1 = ge1 < E;

    // ================= GEMM1 =================
    {
        float c[12][4];
        #pragma unroll
        for (int nt = 0; nt < 12; nt++)
            #pragma unroll
            for (int i = 0; i < 4; i++) c[nt][i] = 0.f;

        #pragma unroll
        for (int ks = 0; ks < 6; ks++) {
            int b0 = (r0 * SA + ks * 16 + tig * 2) * 2;
            int b1 = ((r0 + 8) * SA + ks * 16 + tig * 2) * 2;
            uint32_t Ah[4], Al[4];
            Ah[0] = *(uint32_t*)(sm + O_AHI + b0);
            Ah[1] = *(uint32_t*)(sm + O_AHI + b1);
            Ah[2] = *(uint32_t*)(sm + O_AHI + b0 + 16);
            Ah[3] = *(uint32_t*)(sm + O_AHI + b1 + 16);
            Al[0] = *(uint32_t*)(sm + O_ALO + b0);
            Al[1] = *(uint32_t*)(sm + O_ALO + b1);
            Al[2] = *(uint32_t*)(sm + O_ALO + b0 + 16);
            Al[3] = *(uint32_t*)(sm + O_ALO + b1 + 16);
            #pragma unroll
            for (int nt = 0; nt < 12; nt++) {
                uint2 bh = sF12[((nt * 6 + ks) * 2 + 0) * 32 + lane];
                uint2 bl = sF12[((nt * 6 + ks) * 2 + 1) * 32 + lane];
                mma16816(c[nt], Ah, bh);
                mma16816(c[nt], Al, bh);
                mma16816(c[nt], Ah, bl);
            }
        }
        #pragma unroll
        for (int nt = 0; nt < 12; nt++) {
            int col = nt * 8 + tig * 2;
            float b0v = __ldg(&bm1[col]), b1v = __ldg(&bm1[col + 1]);
            float h00 = fmaxf(c[nt][0] + b0v, 0.f), h01 = fmaxf(c[nt][1] + b1v, 0.f);
            float h10 = fmaxf(c[nt][2] + b0v, 0.f), h11 = fmaxf(c[nt][3] + b1v, 0.f);
            uint32_t hi, lo;
            split2(h00, h01, hi, lo);
            int i0 = (r0 * SH + col) * 2;
            *(uint32_t*)(sm + O_HHI + i0) = hi;
            *(uint32_t*)(sm + O_HLO + i0) = lo;
            split2(h10, h11, hi, lo);
            int i1 = ((r0 + 8) * SH + col) * 2;
            *(uint32_t*)(sm + O_HHI + i1) = hi;
            *(uint32_t*)(sm + O_HLO + i1) = lo;
        }
    }
    __syncthreads();

    // ---- stage F2 frags (F1 done) ----
    for (int i = tid; i < 204 * 32; i += TPB) sF12[i] = gF2[i];
    __syncthreads();

    // ================= GEMM2 =================
    {
        float c[17][4];
        #pragma unroll
        for (int nt = 0; nt < 17; nt++)
            #pragma unroll
            for (int i = 0; i < 4; i++) c[nt][i] = 0.f;

        #pragma unroll
        for (int ks = 0; ks < 6; ks++) {
            int b0 = (r0 * SH + ks * 16 + tig * 2) * 2;
            int b1 = ((r0 + 8) * SH + ks * 16 + tig * 2) * 2;
            uint32_t Ah[4], Al[4];
            Ah[0] = *(uint32_t*)(sm + O_HHI + b0);
            Ah[1] = *(uint32_t*)(sm + O_HHI + b1);
            Ah[2] = *(uint32_t*)(sm + O_HHI + b0 + 16);
            Ah[3] = *(uint32_t*)(sm + O_HHI + b1 + 16);
            Al[0] = *(uint32_t*)(sm + O_HLO + b0);
            Al[1] = *(uint32_t*)(sm + O_HLO + b1);
            Al[2] = *(uint32_t*)(sm + O_HLO + b0 + 16);
            Al[3] = *(uint32_t*)(sm + O_HLO + b1 + 16);
            #pragma unroll
            for (int nt = 0; nt < 17; nt++) {
                uint2 bh = sF12[((nt * 6 + ks) * 2 + 0) * 32 + lane];
                uint2 bl = sF12[((nt * 6 + ks) * 2 + 1) * 32 + lane];
                mma16816(c[nt], Ah, bh);
                mma16816(c[nt], Al, bh);
                mma16816(c[nt], Ah, bl);
            }
        }
        if (tig == 0) {
            float b0v = __ldg(&bm2[0]);
            sK[r0]     = 1.f / (1.f + __expf(-(c[16][0] + b0v)));
            sK[r0 + 8] = 1.f / (1.f + __expf(-(c[16][2] + b0v)));
        }
        __syncwarp();
        float kg0 = sK[r0], kg1 = sK[r0 + 8];
        int d0 = sDst[r0], d1 = sDst[r0 + 8];

        #pragma unroll
        for (int nt = 0; nt < 16; nt++) {
            int col = nt * 8 + tig * 2;
            float b0v = __ldg(&bm2[1 + col]), b1v = __ldg(&bm2[2 + col]);
            float f00 = (c[nt][0] + b0v) * kg0, f01 = (c[nt][1] + b1v) * kg0;
            float f10 = (c[nt][2] + b0v) * kg1, f11 = (c[nt][3] + b1v) * kg1;
            uint32_t hi, lo;
            split2(f00, f01, hi, lo);
            int i0 = (r0 * SA + col) * 2;
            *(uint32_t*)(sm + O_AHI + i0) = hi;
            *(uint32_t*)(sm + O_ALO + i0) = lo;
            split2(f10, f11, hi, lo);
            int i1 = ((r0 + 8) * SA + col) * 2;
            *(uint32_t*)(sm + O_AHI + i1) = hi;
            *(uint32_t*)(sm + O_ALO + i1) = lo;
            if (nt < 4) {
                if (ok0) redadd2(&g_s1[(size_t)d0 * 32 + col], f00, f01);
                if (ok1) redadd2(&g_s1[(size_t)d1 * 32 + col], f10, f11);
            } else if (nt < 8) {
                int cc = col - 32;
                if (ok0) { redmaxu(&g_m2[(size_t)d0 * 32 + cc], encf(f00));
                           redmaxu(&g_m2[(size_t)d0 * 32 + cc + 1], encf(f01)); }
                if (ok1) { redmaxu(&g_m2[(size_t)d1 * 32 + cc], encf(f10));
                           redmaxu(&g_m2[(size_t)d1 * 32 + cc + 1], encf(f11)); }
            } else if (nt < 12) {
                int cc = col - 64;
                if (ok0) { redminu(&g_m3[(size_t)d0 * 32 + cc], encf(f00));
                           redminu(&g_m3[(size_t)d0 * 32 + cc + 1], encf(f01)); }
                if (ok1) { redminu(&g_m3[(size_t)d1 * 32 + cc], encf(f10));
                           redminu(&g_m3[(size_t)d1 * 32 + cc + 1], encf(f11)); }
            } else {
                int cc = col - 96;
                if (ok0) redadd2(&g_m4[(size_t)d0 * 32 + cc], f00, f01);
                if (ok1) redadd2(&g_m4[(size_t)d1 * 32 + cc], f10, f11);
            }
        }
        if (tig == 0) {
            if (ok0) redadd1(&g_deg[d0], 1.f);
            if (ok1) redadd1(&g_deg[d1], 1.f);
        }
    }
    __syncwarp();

    // ================= GEMM3 =================
    {
        float c[4][4];
        #pragma unroll
        for (int nt = 0; nt < 4; nt++)
            #pragma unroll
            for (int i = 0; i < 4; i++) c[nt][i] = 0.f;

        #pragma unroll
        for (int ks = 0; ks < 10; ks++) {
            int b0 = (r0 * SA + ks * 16 + tig * 2) * 2;
            int b1 = ((r0 + 8) * SA + ks * 16 + tig * 2) * 2;
            uint32_t Ah[4], Al[4];
            Ah[0] = *(uint32_t*)(sm + O_AHI + b0);
            Ah[1] = *(uint32_t*)(sm + O_AHI + b1);
            Ah[2] = *(uint32_t*)(sm + O_AHI + b0 + 16);
            Ah[3] = *(uint32_t*)(sm + O_AHI + b1 + 16);
            Al[0] = *(uint32_t*)(sm + O_ALO + b0);
            Al[1] = *(uint32_t*)(sm + O_ALO + b1);
            Al[2] = *(uint32_t*)(sm + O_ALO + b0 + 16);
            Al[3] = *(uint32_t*)(sm + O_ALO + b1 + 16);
            #pragma unroll
            for (int nt = 0; nt < 4; nt++) {
                uint2 bh = sF3[((nt * 10 + ks) * 2 + 0) * 32 + lane];
                uint2 bl = sF3[((nt * 10 + ks) * 2 + 1) * 32 + lane];
                mma16816(c[nt], Ah, bh);
                mma16816(c[nt], Al, bh);
                mma16816(c[nt], Ah, bl);
            }
        }
        #pragma unroll
        for (int nt = 0; nt < 4; nt++) {
            int col = nt * 8 + tig * 2;
            float b0v = __ldg(&be[col]), b1v = __ldg(&be[col + 1]);
            if (ok0) {
                float2 r = make_float2(c[nt][0] + b0v, c[nt][1] + b1v);
                *(float2*)(out_ve + (size_t)ge0 * 32 + col) = r;
            }
            if (ok1) {
                float2 r = make_float2(c[nt][2] + b0v, c[nt][3] + b1v);
                *(float2*)(out_ve + (size_t)ge1 * 32 + col) = r;
            }
        }
    }
}

// ================= node update via mma =================
__global__ __launch_bounds__(TPB, 1)
void node_mma_kernel(const float* __restrict__ vc, const float* __restrict__ br,
                     float* __restrict__ out_vc, int N)
{
    extern __shared__ char sm[];
    const int tid  = threadIdx.x;
    const int lane = tid & 31;
    const int wid  = tid >> 5;
    const int g    = lane >> 2;
    const int tig  = lane & 3;
    const int nBase = blockIdx.x * 128;

    // ---- gather node features: 2 threads per node ----
    {
        int row = tid >> 1, half = tid & 1;
        int n = nBase + row;
        int nc = (n < N) ? n : (N - 1);
        float deg = g_deg[nc];
        bool has = deg > 0.f;
        float rdeg = 1.f / fmaxf(deg, 1.f);

        auto put4 = [&](int col, float4 v) {
            uint32_t h0, l0, h1, l1;
            split2(v.x, v.y, h0, l0);
            split2(v.z, v.w, h1, l1);
            int idx = (row * SA + col) * 2;
            *(uint2*)(sm + ON_AHI + idx) = make_uint2(h0, h1);
            *(uint2*)(sm + ON_ALO + idx) = make_uint2(l0, l1);
        };
        // 40 float4-chunks: [0..7]=vc, [8..15]=s1, [16..23]=m2, [24..31]=m3, [32..39]=m4
        for (int q = half; q < 40; q += 2) {
            float4 v;
            if (q < 8) {
                v = ((const float4*)(vc + (size_t)nc * 32))[q];
            } else if (q < 16) {
                v = ((const float4*)(g_s1 + (size_t)nc * 32))[q - 8];
            } else if (q < 24) {
                uint4 u = ((const uint4*)(g_m2 + (size_t)nc * 32))[q - 16];
                v = has ? make_float4(decf(u.x), decf(u.y), decf(u.z), decf(u.w))
                        : make_float4(0.f, 0.f, 0.f, 0.f);
            } else if (q < 32) {
                uint4 u = ((const uint4*)(g_m3 + (size_t)nc * 32))[q - 24];
                v = has ? make_float4(decf(u.x), decf(u.y), decf(u.z), decf(u.w))
                        : make_float4(0.f, 0.f, 0.f, 0.f);
            } else {
                float4 s = ((const float4*)(g_m4 + (size_t)nc * 32))[q - 32];
                v = make_float4(s.x * rdeg, s.y * rdeg, s.z * rdeg, s.w * rdeg);
            }
            put4(q * 4, v);
        }
    }
    __syncthreads();

    const int r0 = wid * 16 + g;
    const int n0 = nBase + r0, n1 = n0 + 8;

    float c[4][4];
    #pragma unroll
    for (int nt = 0; nt < 4; nt++)
        #pragma unroll
        for (int i = 0; i < 4; i++) c[nt][i] = 0.f;

    #pragma unroll
    for (int ks = 0; ks < 10; ks++) {
        int b0 = (r0 * SA + ks * 16 + tig * 2) * 2;
        int b1 = ((r0 + 8) * SA + ks * 16 + tig * 2) * 2;
        uint32_t Ah[4], Al[4];
        Ah[0] = *(uint32_t*)(sm + ON_AHI + b0);
        Ah[1] = *(uint32_t*)(sm + ON_AHI + b1);
        Ah[2] = *(uint32_t*)(sm + ON_AHI + b0 + 16);
        Ah[3] = *(uint32_t*)(sm + ON_AHI + b1 + 16);
        Al[0] = *(uint32_t*)(sm + ON_ALO + b0);
        Al[1] = *(uint32_t*)(sm + ON_ALO + b1);
        Al[2] = *(uint32_t*)(sm + ON_ALO + b0 + 16);
        Al[3] = *(uint32_t*)(sm + ON_ALO + b1 + 16);
        #pragma unroll
        for (int nt = 0; nt < 4; nt++) {
            uint2 bh = gFr[((nt * 10 + ks) * 2 + 0) * 32 + lane];
            uint2 bl = gFr[((nt * 10 + ks) * 2 + 1) * 32 + lane];
            mma16816(c[nt], Ah, bh);
            mma16816(c[nt], Al, bh);
            mma16816(c[nt], Ah, bl);
        }
    }
    #pragma unroll
    for (int nt = 0; nt < 4; nt++) {
        int col = nt * 8 + tig * 2;
        float b0v = __ldg(&br[col]), b1v = __ldg(&br[col + 1]);
        if (n0 < N) {
            float2 r = make_float2(c[nt][0] + b0v, c[nt][1] + b1v);
            *(float2*)(out_vc + (size_t)n0 * 32 + col) = r;
        }
        if (n1 < N) {
            float2 r = make_float2(c[nt][2] + b0v, c[nt][3] + b1v);
            *(float2*)(out_vc + (size_t)n1 * 32 + col) = r;
        }
    }
}

extern "C" void kernel_launch(void* const* d_in, const int* in_sizes, int n_in,
                              void* d_out, int out_size)
{
    const float* vc  = (const float*)d_in[0];
    const float* ve  = (const float*)d_in[1];
    const int*   src = (const int*)d_in[2];
    const int*   dst = (const int*)d_in[3];
    const float* Wm1 = (const float*)d_in[4];
    const float* bm1 = (const float*)d_in[5];
    const float* Wm2 = (const float*)d_in[6];
    const float* bm2 = (const float*)d_in[7];
    const float* Wr  = (const float*)d_in[8];
    const float* br  = (const float*)d_in[9];
    const float* We  = (const float*)d_in[10];
    const float* be  = (const float*)d_in[11];

    int N = in_sizes[0] / 32;
    int E = in_sizes[2];

    float* out_vc = (float*)d_out;
    float* out_ve = out_vc + (size_t)N * 32;

    cudaFuncSetAttribute(edge_kernel, cudaFuncAttributeMaxDynamicSharedMemorySize, SMEMB);
    cudaFuncSetAttribute(node_mma_kernel, cudaFuncAttributeMaxDynamicSharedMemorySize, NSMEMB);

    prep_kernel<<<(508 * 32 + 255) / 256, 256>>>(Wm1, Wm2, We, Wr);
    init_kernel<<<(N * 8 + 255) / 256, 256>>>(N);
    edge_kernel<<<(E + BE - 1) / BE, TPB, SMEMB>>>(
        vc, ve, src, dst, bm1, bm2, be, out_ve, E);
    node_mma_kernel<<<(N + 127) / 128, TPB, NSMEMB>>>(vc, br, out_vc, N);
}